// round 2
// baseline (speedup 1.0000x reference)
#include <cuda_runtime.h>
#include <cstdint>

// InteractingSites: per-frame all-pairs soft-core Coulomb, packed-f32x2 tile design.
//
// B frames x S=128 sites (contiguous per frame).
// energy[f] = sum_{i<j} q_i q_j * rsqrt(|p_i-p_j|^2 + 1e-6)
//
// ONE WARP per frame. Sites split into 4 tiles T0..T3 of 32; lane l owns rows
// T0[l], T1[l], T2[l], T3[l] in registers, packed pairwise as f32x2:
//   ab = (T0[l], T1[l]),  ac = (T0[l], T2[l]),  cd = (T2[l], T3[l])
//
// Pair enumeration (each unordered pair exactly once):
//  Rectangles (6144 pairs), warp-uniform m = 0..31 (broadcast LDS):
//    g1: ab vs dup(T2[m])        -> {T0xT2, T1xT2}
//    g2: ab vs dup(T3[m])        -> {T0xT3, T1xT3}
//    g3: ac vs (T1[m], T3[m])    -> {T0xT1, T2xT3}
//  Triangles (1984 pairs), lane-varying m = (l+dd)&31, SoA conflict-free LDS:
//    dd=1..15: ab vs (T0[m],T1[m]) ; cd vs (T2[m],T3[m])
//    dd=16, lanes 0..15 only: same two groups.
//
// j-site shared layouts store NEGATED coords so dx = add.f32x2(row, jneg);
// charges stored positive. One MUFU.RSQ per 32 pairs (hard floor).

#define WARPS_PER_CTA 4
#define S_SITES 128
// bit pattern of 1e-6f duplicated into both f32x2 halves
#define EPS2_PACKED 0x358637BD358637BDULL

using u64 = unsigned long long;

__device__ __forceinline__ u64 pk2(float lo, float hi) {
    u64 r;
    asm("mov.b64 %0, {%1, %2};" : "=l"(r) : "f"(lo), "f"(hi));
    return r;
}
__device__ __forceinline__ void unpk2(u64 v, float& lo, float& hi) {
    asm("mov.b64 {%0, %1}, %2;" : "=f"(lo), "=f"(hi) : "l"(v));
}
__device__ __forceinline__ u64 add2(u64 a, u64 b) {
    u64 d;
    asm("add.rn.f32x2 %0, %1, %2;" : "=l"(d) : "l"(a), "l"(b));
    return d;
}
__device__ __forceinline__ u64 mul2(u64 a, u64 b) {
    u64 d;
    asm("mul.rn.f32x2 %0, %1, %2;" : "=l"(d) : "l"(a), "l"(b));
    return d;
}
__device__ __forceinline__ u64 fma2(u64 a, u64 b, u64 c) {
    u64 d;
    asm("fma.rn.f32x2 %0, %1, %2, %3;" : "=l"(d) : "l"(a), "l"(b), "l"(c));
    return d;
}
__device__ __forceinline__ u64 rsqrt2(u64 v) {
    float lo, hi;
    unpk2(v, lo, hi);
    float rl, rh;
    asm("rsqrt.approx.f32 %0, %1;" : "=f"(rl) : "f"(lo));
    asm("rsqrt.approx.f32 %0, %1;" : "=f"(rh) : "f"(hi));
    return pk2(rl, rh);
}

// one packed interaction group: rows (rx,ry,rz,rq) vs j (jx,jy,jz negated, jq)
__device__ __forceinline__ void pair_acc(u64 rx, u64 ry, u64 rz, u64 rq,
                                         u64 jx, u64 jy, u64 jz, u64 jq,
                                         u64& acc) {
    u64 dx = add2(rx, jx);
    u64 dy = add2(ry, jy);
    u64 dz = add2(rz, jz);
    u64 r2 = fma2(dz, dz, (u64)EPS2_PACKED);
    r2 = fma2(dy, dy, r2);
    r2 = fma2(dx, dx, r2);
    u64 rs = rsqrt2(r2);
    u64 qq = mul2(rq, jq);
    acc = fma2(qq, rs, acc);
}

__global__ __launch_bounds__(WARPS_PER_CTA * 32)
void interacting_sites_kernel(const float* __restrict__ positions,
                              const float* __restrict__ charges,
                              float* __restrict__ out,
                              int num_frames) {
    // AoS (broadcast, rect loop): [warp][0:dupT2, 1:dupT3, 2:(T1,T3)][m][x,y,z,q]
    __shared__ u64 aos[WARPS_PER_CTA][3][32][4];
    // SoA (lane-varying, triangle loop): [warp][0:(T0,T1), 1:(T2,T3)][x,y,z,q][m]
    __shared__ u64 soa[WARPS_PER_CTA][2][4][32];

    const int w = threadIdx.x >> 5;
    const int l = threadIdx.x & 31;
    const int fid = blockIdx.x * WARPS_PER_CTA + w;
    if (fid >= num_frames) return;  // whole warp exits; no cross-warp sync used

    // Load lane's 4 sites (one per tile)
    const long long base = (long long)fid * S_SITES;
    float sx[4], sy[4], sz[4], sq[4];
#pragma unroll
    for (int k = 0; k < 4; ++k) {
        const long long idx = base + k * 32 + l;
        const float* p = positions + idx * 3;
        sx[k] = p[0];
        sy[k] = p[1];
        sz[k] = p[2];
        sq[k] = charges[idx];
    }

    // Populate shared j-layouts (coords negated, charges positive)
    // dup(T2[l]):
    aos[w][0][l][0] = pk2(-sx[2], -sx[2]);
    aos[w][0][l][1] = pk2(-sy[2], -sy[2]);
    aos[w][0][l][2] = pk2(-sz[2], -sz[2]);
    aos[w][0][l][3] = pk2( sq[2],  sq[2]);
    // dup(T3[l]):
    aos[w][1][l][0] = pk2(-sx[3], -sx[3]);
    aos[w][1][l][1] = pk2(-sy[3], -sy[3]);
    aos[w][1][l][2] = pk2(-sz[3], -sz[3]);
    aos[w][1][l][3] = pk2( sq[3],  sq[3]);
    // (T1[l], T3[l]):
    aos[w][2][l][0] = pk2(-sx[1], -sx[3]);
    aos[w][2][l][1] = pk2(-sy[1], -sy[3]);
    aos[w][2][l][2] = pk2(-sz[1], -sz[3]);
    aos[w][2][l][3] = pk2( sq[1],  sq[3]);
    // SoA (T0[l], T1[l]):
    soa[w][0][0][l] = pk2(-sx[0], -sx[1]);
    soa[w][0][1][l] = pk2(-sy[0], -sy[1]);
    soa[w][0][2][l] = pk2(-sz[0], -sz[1]);
    soa[w][0][3][l] = pk2( sq[0],  sq[1]);
    // SoA (T2[l], T3[l]):
    soa[w][1][0][l] = pk2(-sx[2], -sx[3]);
    soa[w][1][1][l] = pk2(-sy[2], -sy[3]);
    soa[w][1][2][l] = pk2(-sz[2], -sz[3]);
    soa[w][1][3][l] = pk2( sq[2],  sq[3]);
    __syncwarp();

    // Packed row registers
    const u64 ab_x = pk2(sx[0], sx[1]), ab_y = pk2(sy[0], sy[1]),
              ab_z = pk2(sz[0], sz[1]), ab_q = pk2(sq[0], sq[1]);
    const u64 ac_x = pk2(sx[0], sx[2]), ac_y = pk2(sy[0], sy[2]),
              ac_z = pk2(sz[0], sz[2]), ac_q = pk2(sq[0], sq[2]);
    const u64 cd_x = pk2(sx[2], sx[3]), cd_y = pk2(sy[2], sy[3]),
              cd_z = pk2(sz[2], sz[3]), cd_q = pk2(sq[2], sq[3]);

    u64 acc0 = 0ULL, acc1 = 0ULL, acc2 = 0ULL;  // packed (0.0f, 0.0f)

    // ── Rectangles: warp-uniform m, broadcast LDS ──
#pragma unroll 4
    for (int m = 0; m < 32; ++m) {
        {   // g1: ab vs dup(T2[m])
            const ulonglong2 jxy = *reinterpret_cast<const ulonglong2*>(&aos[w][0][m][0]);
            const ulonglong2 jzq = *reinterpret_cast<const ulonglong2*>(&aos[w][0][m][2]);
            pair_acc(ab_x, ab_y, ab_z, ab_q, jxy.x, jxy.y, jzq.x, jzq.y, acc0);
        }
        {   // g2: ab vs dup(T3[m])
            const ulonglong2 jxy = *reinterpret_cast<const ulonglong2*>(&aos[w][1][m][0]);
            const ulonglong2 jzq = *reinterpret_cast<const ulonglong2*>(&aos[w][1][m][2]);
            pair_acc(ab_x, ab_y, ab_z, ab_q, jxy.x, jxy.y, jzq.x, jzq.y, acc0);
        }
        {   // g3: ac vs (T1[m], T3[m])
            const ulonglong2 jxy = *reinterpret_cast<const ulonglong2*>(&aos[w][2][m][0]);
            const ulonglong2 jzq = *reinterpret_cast<const ulonglong2*>(&aos[w][2][m][2]);
            pair_acc(ac_x, ac_y, ac_z, ac_q, jxy.x, jxy.y, jzq.x, jzq.y, acc1);
        }
    }

    // ── Triangles: lane-varying m, SoA conflict-free LDS ──
#pragma unroll 5
    for (int dd = 1; dd < 16; ++dd) {
        const int m = (l + dd) & 31;
        pair_acc(ab_x, ab_y, ab_z, ab_q,
                 soa[w][0][0][m], soa[w][0][1][m], soa[w][0][2][m], soa[w][0][3][m],
                 acc0);
        pair_acc(cd_x, cd_y, cd_z, cd_q,
                 soa[w][1][0][m], soa[w][1][1][m], soa[w][1][2][m], soa[w][1][3][m],
                 acc2);
    }
    // dd = 16: each opposite pair once (lanes 0..15 only)
    if (l < 16) {
        const int m = l + 16;
        pair_acc(ab_x, ab_y, ab_z, ab_q,
                 soa[w][0][0][m], soa[w][0][1][m], soa[w][0][2][m], soa[w][0][3][m],
                 acc0);
        pair_acc(cd_x, cd_y, cd_z, cd_q,
                 soa[w][1][0][m], soa[w][1][1][m], soa[w][1][2][m], soa[w][1][3][m],
                 acc2);
    }

    // Reduce: unpack 3 packed accumulators -> lane sum -> warp sum
    float a0l, a0h, a1l, a1h, a2l, a2h;
    unpk2(acc0, a0l, a0h);
    unpk2(acc1, a1l, a1h);
    unpk2(acc2, a2l, a2h);
    float s = ((a0l + a0h) + (a1l + a1h)) + (a2l + a2h);
#pragma unroll
    for (int o = 16; o > 0; o >>= 1)
        s += __shfl_xor_sync(0xFFFFFFFFu, s, o);
    if (l == 0) out[fid] = s;
}

extern "C" void kernel_launch(void* const* d_in, const int* in_sizes, int n_in,
                              void* d_out, int out_size) {
    const float* positions = (const float*)d_in[0];  // [N,3] f32
    const float* charges   = (const float*)d_in[1];  // [N]   f32
    float* out = (float*)d_out;                      // [B]   f32

    const int num_frames = out_size;
    const int grid = (num_frames + WARPS_PER_CTA - 1) / WARPS_PER_CTA;
    interacting_sites_kernel<<<grid, WARPS_PER_CTA * 32>>>(positions, charges, out,
                                                           num_frames);
}

// round 3
// speedup vs baseline: 1.1373x; 1.1373x over previous
#include <cuda_runtime.h>
#include <cstdint>

// InteractingSites: per-frame all-pairs soft-core Coulomb.
// Packed-f32x2 math (R2) + 4-warps-per-frame work split (restores occupancy).
//
// CTA = 1 frame = 128 threads = 4 warps. Sites split into tiles T0..T3 of 32;
// lane l holds T0[l]..T3[l]; packed row registers:
//   ab=(T0,T1)  ac=(T0,T2)  cd=(T2,T3)
//
// Group enumeration (each unordered pair exactly once), split across warps:
//  Rectangles: m = 0..31, 3 packed groups per m -> warp w takes m in [8w, 8w+8)
//    g1: ab vs dup(T2[m])     g2: ab vs dup(T3[m])     g3: ac vs (T1[m],T3[m])
//  Triangles: lane-varying m=(l+dd)&31, 2 packed groups per dd
//    warp w in {0,1,2}: dd in [1+4w, 5+4w) ; warp 3: dd 13,14,15 + masked dd=16

#define S_SITES 128
#define EPS2_PACKED 0x358637BD358637BDULL  // (1e-6f, 1e-6f)

using u64 = unsigned long long;

__device__ __forceinline__ u64 pk2(float lo, float hi) {
    u64 r;
    asm("mov.b64 %0, {%1, %2};" : "=l"(r) : "f"(lo), "f"(hi));
    return r;
}
__device__ __forceinline__ void unpk2(u64 v, float& lo, float& hi) {
    asm("mov.b64 {%0, %1}, %2;" : "=f"(lo), "=f"(hi) : "l"(v));
}
__device__ __forceinline__ u64 add2(u64 a, u64 b) {
    u64 d;
    asm("add.rn.f32x2 %0, %1, %2;" : "=l"(d) : "l"(a), "l"(b));
    return d;
}
__device__ __forceinline__ u64 mul2(u64 a, u64 b) {
    u64 d;
    asm("mul.rn.f32x2 %0, %1, %2;" : "=l"(d) : "l"(a), "l"(b));
    return d;
}
__device__ __forceinline__ u64 fma2(u64 a, u64 b, u64 c) {
    u64 d;
    asm("fma.rn.f32x2 %0, %1, %2, %3;" : "=l"(d) : "l"(a), "l"(b), "l"(c));
    return d;
}
__device__ __forceinline__ u64 rsqrt2(u64 v) {
    float lo, hi;
    unpk2(v, lo, hi);
    float rl, rh;
    asm("rsqrt.approx.f32 %0, %1;" : "=f"(rl) : "f"(lo));
    asm("rsqrt.approx.f32 %0, %1;" : "=f"(rh) : "f"(hi));
    return pk2(rl, rh);
}

__device__ __forceinline__ void pair_acc(u64 rx, u64 ry, u64 rz, u64 rq,
                                         u64 jx, u64 jy, u64 jz, u64 jq,
                                         u64& acc) {
    u64 dx = add2(rx, jx);  // j coords stored negated
    u64 dy = add2(ry, jy);
    u64 dz = add2(rz, jz);
    u64 r2 = fma2(dz, dz, (u64)EPS2_PACKED);
    r2 = fma2(dy, dy, r2);
    r2 = fma2(dx, dx, r2);
    u64 rs = rsqrt2(r2);
    u64 qq = mul2(rq, jq);
    acc = fma2(qq, rs, acc);
}

__global__ __launch_bounds__(S_SITES)
void interacting_sites_kernel(const float* __restrict__ positions,
                              const float* __restrict__ charges,
                              float* __restrict__ out) {
    // AoS (broadcast, rect loop): [0:dupT2, 1:dupT3, 2:(T1,T3)][m][x,y,z,q]
    __shared__ u64 aos[3][32][4];
    // SoA (lane-varying, triangle loop): [0:(T0,T1), 1:(T2,T3)][x,y,z,q][m]
    __shared__ u64 soa[2][4][32];
    __shared__ float warp_sum[4];

    const int fid = blockIdx.x;
    const int w = threadIdx.x >> 5;
    const int l = threadIdx.x & 31;

    // Every warp loads the same 4x32 site table into its registers
    const long long base = (long long)fid * S_SITES;
    float sx[4], sy[4], sz[4], sq[4];
#pragma unroll
    for (int k = 0; k < 4; ++k) {
        const long long idx = base + k * 32 + l;
        const float* p = positions + idx * 3;
        sx[k] = p[0];
        sy[k] = p[1];
        sz[k] = p[2];
        sq[k] = charges[idx];
    }

    // Warp 0 builds the shared j-tables (coords negated, charges positive)
    if (w == 0) {
        aos[0][l][0] = pk2(-sx[2], -sx[2]);
        aos[0][l][1] = pk2(-sy[2], -sy[2]);
        aos[0][l][2] = pk2(-sz[2], -sz[2]);
        aos[0][l][3] = pk2( sq[2],  sq[2]);
        aos[1][l][0] = pk2(-sx[3], -sx[3]);
        aos[1][l][1] = pk2(-sy[3], -sy[3]);
        aos[1][l][2] = pk2(-sz[3], -sz[3]);
        aos[1][l][3] = pk2( sq[3],  sq[3]);
        aos[2][l][0] = pk2(-sx[1], -sx[3]);
        aos[2][l][1] = pk2(-sy[1], -sy[3]);
        aos[2][l][2] = pk2(-sz[1], -sz[3]);
        aos[2][l][3] = pk2( sq[1],  sq[3]);
        soa[0][0][l] = pk2(-sx[0], -sx[1]);
        soa[0][1][l] = pk2(-sy[0], -sy[1]);
        soa[0][2][l] = pk2(-sz[0], -sz[1]);
        soa[0][3][l] = pk2( sq[0],  sq[1]);
        soa[1][0][l] = pk2(-sx[2], -sx[3]);
        soa[1][1][l] = pk2(-sy[2], -sy[3]);
        soa[1][2][l] = pk2(-sz[2], -sz[3]);
        soa[1][3][l] = pk2( sq[2],  sq[3]);
    }
    __syncthreads();

    const u64 ab_x = pk2(sx[0], sx[1]), ab_y = pk2(sy[0], sy[1]),
              ab_z = pk2(sz[0], sz[1]), ab_q = pk2(sq[0], sq[1]);
    const u64 ac_x = pk2(sx[0], sx[2]), ac_y = pk2(sy[0], sy[2]),
              ac_z = pk2(sz[0], sz[2]), ac_q = pk2(sq[0], sq[2]);
    const u64 cd_x = pk2(sx[2], sx[3]), cd_y = pk2(sy[2], sy[3]),
              cd_z = pk2(sz[2], sz[3]), cd_q = pk2(sq[2], sq[3]);

    u64 acc0 = 0ULL, acc1 = 0ULL, acc2 = 0ULL;

    // ── Rectangles: this warp handles m in [8w, 8w+8) ──
    const int m0 = w << 3;
#pragma unroll
    for (int i = 0; i < 8; ++i) {
        const int m = m0 + i;
        {
            const ulonglong2 jxy = *reinterpret_cast<const ulonglong2*>(&aos[0][m][0]);
            const ulonglong2 jzq = *reinterpret_cast<const ulonglong2*>(&aos[0][m][2]);
            pair_acc(ab_x, ab_y, ab_z, ab_q, jxy.x, jxy.y, jzq.x, jzq.y, acc0);
        }
        {
            const ulonglong2 jxy = *reinterpret_cast<const ulonglong2*>(&aos[1][m][0]);
            const ulonglong2 jzq = *reinterpret_cast<const ulonglong2*>(&aos[1][m][2]);
            pair_acc(ab_x, ab_y, ab_z, ab_q, jxy.x, jxy.y, jzq.x, jzq.y, acc0);
        }
        {
            const ulonglong2 jxy = *reinterpret_cast<const ulonglong2*>(&aos[2][m][0]);
            const ulonglong2 jzq = *reinterpret_cast<const ulonglong2*>(&aos[2][m][2]);
            pair_acc(ac_x, ac_y, ac_z, ac_q, jxy.x, jxy.y, jzq.x, jzq.y, acc1);
        }
    }

    // ── Triangles: warps 0..2 take dd in [1+4w, 5+4w); warp 3 takes 13..15 + dd=16 ──
    const int dd0 = 1 + (w << 2);
#pragma unroll
    for (int i = 0; i < 4; ++i) {
        const int dd = dd0 + i;
        if (dd < 16) {
            const int m = (l + dd) & 31;
            pair_acc(ab_x, ab_y, ab_z, ab_q,
                     soa[0][0][m], soa[0][1][m], soa[0][2][m], soa[0][3][m], acc0);
            pair_acc(cd_x, cd_y, cd_z, cd_q,
                     soa[1][0][m], soa[1][1][m], soa[1][2][m], soa[1][3][m], acc2);
        }
    }
    if (w == 3 && l < 16) {   // dd = 16: each opposite pair once
        const int m = l + 16;
        pair_acc(ab_x, ab_y, ab_z, ab_q,
                 soa[0][0][m], soa[0][1][m], soa[0][2][m], soa[0][3][m], acc0);
        pair_acc(cd_x, cd_y, cd_z, cd_q,
                 soa[1][0][m], soa[1][1][m], soa[1][2][m], soa[1][3][m], acc2);
    }

    // Reduce: packed accs -> lane scalar -> warp -> CTA
    float a0l, a0h, a1l, a1h, a2l, a2h;
    unpk2(acc0, a0l, a0h);
    unpk2(acc1, a1l, a1h);
    unpk2(acc2, a2l, a2h);
    float s = ((a0l + a0h) + (a1l + a1h)) + (a2l + a2h);
#pragma unroll
    for (int o = 16; o > 0; o >>= 1)
        s += __shfl_xor_sync(0xFFFFFFFFu, s, o);
    if (l == 0) warp_sum[w] = s;
    __syncthreads();
    if (threadIdx.x == 0)
        out[fid] = (warp_sum[0] + warp_sum[1]) + (warp_sum[2] + warp_sum[3]);
}

extern "C" void kernel_launch(void* const* d_in, const int* in_sizes, int n_in,
                              void* d_out, int out_size) {
    const float* positions = (const float*)d_in[0];  // [N,3] f32
    const float* charges   = (const float*)d_in[1];  // [N]   f32
    float* out = (float*)d_out;                      // [B]   f32

    const int num_frames = out_size;
    interacting_sites_kernel<<<num_frames, S_SITES>>>(positions, charges, out);
}